// round 7
// baseline (speedup 1.0000x reference)
#include <cuda_runtime.h>
#include <cuda_bf16.h>
#include <cstdint>

// RandomPooling: y[b,c,h,w] = x[b,c, refl(h+rh[b,h,w]-1), refl(w+rw[b,h,w]-1)]
// B=32, C=3, H=W=512, GAP=1 reflect padding.
// HBM-bound gather, ~235-267 MB DRAM traffic. R3: 39.1us @ 6.0TB/s (76%).
// R4: 8 px/thread (2x ILP) + evict-first hints on touch-once streams.

static constexpr int B = 32;
static constexpr int C = 3;
static constexpr int H = 512;
static constexpr int W = 512;
static constexpr int HW = H * W;          // 262144 = 1<<18
static constexpr int LOG_HW = 18;
static constexpr int LOG_W = 9;
static constexpr int PX = 8;              // pixels per thread

__device__ __forceinline__ int refl(int s, int n) {
    // GAP=1: s in [-1, n]. reflect: -1 -> 1, n -> n-2.
    if (s < 0) s = -s;
    if (s >= n) s = 2 * n - 2 - s;
    return s;
}

__global__ __launch_bounds__(256)
void random_pool_kernel(const float* __restrict__ x,
                        const int*   __restrict__ rh,
                        const int*   __restrict__ rw,
                        float*       __restrict__ out)
{
    // Each thread handles 8 consecutive w-pixels of one (b,h) row.
    int t = blockIdx.x * blockDim.x + threadIdx.x;
    int pix = t << 3;                      // first pixel index (b*HW + h*W + w)
    if (pix >= B * HW) return;

    int b  = pix >> LOG_HW;
    int hw = pix & (HW - 1);
    int h  = hw >> LOG_W;
    int w  = hw & (W - 1);                 // multiple of 8

    // Index streams are touch-once: evict-first so they don't pollute L2
    // (L2 capacity is better spent on x rows, which get ~3x reuse).
    int4 rha = __ldcs(reinterpret_cast<const int4*>(rh + pix));
    int4 rhb = __ldcs(reinterpret_cast<const int4*>(rh + pix + 4));
    int4 rwa = __ldcs(reinterpret_cast<const int4*>(rw + pix));
    int4 rwb = __ldcs(reinterpret_cast<const int4*>(rw + pix + 4));

    // Source offsets within one channel plane (shared across all 3 channels)
    int src[PX];
    {
        int rhv[PX] = {rha.x, rha.y, rha.z, rha.w, rhb.x, rhb.y, rhb.z, rhb.w};
        int rwv[PX] = {rwa.x, rwa.y, rwa.z, rwa.w, rwb.x, rwb.y, rwb.z, rwb.w};
        #pragma unroll
        for (int i = 0; i < PX; i++) {
            int sh = refl(h + rhv[i] - 1, H);
            int sw = refl(w + i + rwv[i] - 1, W);
            src[i] = (sh << LOG_W) + sw;
        }
    }

    // Per-channel gather + vectorized streaming stores.
    // All offsets fit in 32 bits (max plane offset 96*2^18 < 2^25 elems).
    unsigned plane = (unsigned)(b * C) << LOG_HW;   // channel-0 plane offset
    #pragma unroll
    for (int c = 0; c < C; c++) {
        const float* __restrict__ xc = x + plane;
        float v[PX];
        #pragma unroll
        for (int i = 0; i < PX; i++) v[i] = __ldg(xc + src[i]);

        float* oc = out + plane + hw;
        // Output is touch-once: streaming stores (evict-first in L2).
        __stcs(reinterpret_cast<float4*>(oc),     make_float4(v[0], v[1], v[2], v[3]));
        __stcs(reinterpret_cast<float4*>(oc) + 1, make_float4(v[4], v[5], v[6], v[7]));
        plane += HW;
    }
}

extern "C" void kernel_launch(void* const* d_in, const int* in_sizes, int n_in,
                              void* d_out, int out_size)
{
    const float* x  = (const float*)d_in[0];
    const int*   rh = (const int*)d_in[1];
    const int*   rw = (const int*)d_in[2];
    float*       y  = (float*)d_out;

    const int n_pix = B * HW;              // 8,388,608
    const int threads = 256;
    const int blocks = (n_pix / PX + threads - 1) / threads;   // 4096
    random_pool_kernel<<<blocks, threads>>>(x, rh, rw, y);
}

// round 9
// speedup vs baseline: 1.2089x; 1.2089x over previous
#include <cuda_runtime.h>
#include <cuda_bf16.h>
#include <cstdint>

// RandomPooling: y[b,c,h,w] = x[b,c, refl(h+rh[b,h,w]-1), refl(w+rw[b,h,w]-1)]
// B=32, C=3, H=W=512, GAP=1 reflect padding.
// HBM-bound gather, traffic ~237 MB (at floor).
// R3 (PX=4, no hints): 39.1us @ 6.0TB/s, DRAM 76%.
// R7 (PX=8 + hints):   49.5us @ 4.8TB/s — REGRESSION: per-thread-contiguous
//   32B chunks halve store-wavefront density (2x L1tex store wavefronts,
//   each 128B line split across two STGs) and sparsen gather wavefronts.
// R8: back to PX=4 interleaved layout (full-density wavefronts); isolate the
//   cache hints as the single variable (__ldcs indices, __stcs output).

static constexpr int B = 32;
static constexpr int C = 3;
static constexpr int H = 512;
static constexpr int W = 512;
static constexpr int HW = H * W;          // 262144 = 1<<18
static constexpr int LOG_HW = 18;
static constexpr int LOG_W = 9;

__device__ __forceinline__ int refl(int s, int n) {
    // GAP=1: s in [-1, n]. reflect: -1 -> 1, n -> n-2.
    if (s < 0) s = -s;
    if (s >= n) s = 2 * n - 2 - s;
    return s;
}

__global__ __launch_bounds__(256)
void random_pool_kernel(const float* __restrict__ x,
                        const int*   __restrict__ rh,
                        const int*   __restrict__ rw,
                        float*       __restrict__ out)
{
    // Each thread handles 4 consecutive w-pixels of one (b,h) row.
    // One float4 per thread -> warp store = 512B contiguous (full-density).
    int t = blockIdx.x * blockDim.x + threadIdx.x;
    int pix = t << 2;                      // first pixel index (b*HW + h*W + w)
    if (pix >= B * HW) return;

    int b  = pix >> LOG_HW;
    int hw = pix & (HW - 1);
    int h  = hw >> LOG_W;
    int w  = hw & (W - 1);                 // multiple of 4

    // Touch-once index streams: evict-first in L2 (keep capacity for x rows,
    // which are re-read by ~3 output rows each).
    int4 rh4 = __ldcs(reinterpret_cast<const int4*>(rh + pix));
    int4 rw4 = __ldcs(reinterpret_cast<const int4*>(rw + pix));

    // Source offsets within one channel plane (shared across all 3 channels)
    int sh0 = refl(h + rh4.x - 1, H);
    int sh1 = refl(h + rh4.y - 1, H);
    int sh2 = refl(h + rh4.z - 1, H);
    int sh3 = refl(h + rh4.w - 1, H);

    int sw0 = refl(w + 0 + rw4.x - 1, W);
    int sw1 = refl(w + 1 + rw4.y - 1, W);
    int sw2 = refl(w + 2 + rw4.z - 1, W);
    int sw3 = refl(w + 3 + rw4.w - 1, W);

    int src0 = (sh0 << LOG_W) + sw0;
    int src1 = (sh1 << LOG_W) + sw1;
    int src2 = (sh2 << LOG_W) + sw2;
    int src3 = (sh3 << LOG_W) + sw3;

    // Per-channel gather + full-density coalesced streaming store.
    unsigned plane = (unsigned)(b * C) << LOG_HW;   // channel-0 plane offset
    #pragma unroll
    for (int c = 0; c < C; c++) {
        const float* __restrict__ xc = x + plane;
        float4 v;
        v.x = __ldg(xc + src0);
        v.y = __ldg(xc + src1);
        v.z = __ldg(xc + src2);
        v.w = __ldg(xc + src3);
        // Touch-once output: evict-first. Warp writes 512B contiguous,
        // so every 128B line is fully covered by one wavefront.
        __stcs(reinterpret_cast<float4*>(out + plane + hw), v);
        plane += HW;
    }
}

extern "C" void kernel_launch(void* const* d_in, const int* in_sizes, int n_in,
                              void* d_out, int out_size)
{
    const float* x  = (const float*)d_in[0];
    const int*   rh = (const int*)d_in[1];
    const int*   rw = (const int*)d_in[2];
    float*       y  = (float*)d_out;

    const int n_pix = B * HW;              // 8,388,608
    const int threads = 256;
    const int blocks = (n_pix / 4 + threads - 1) / threads;   // 8192
    random_pool_kernel<<<blocks, threads>>>(x, rh, rw, y);
}